// round 5
// baseline (speedup 1.0000x reference)
#include <cuda_runtime.h>

#define TT 128          // threads per block == rows per block
#define NSTEPS 16

// ---------------------------------------------------------------------------
// Shared layout (per CTA), stride TT per vector index, thread-private columns:
//   sy[64], sz[64], skx[64], svx[64], sA[64], sB[64]  -> 384 floats/row
//   384 * 128 * 4B = 196608 B dynamic shared
// ---------------------------------------------------------------------------

__device__ __forceinline__ float gelu_exact(float v) {
    return 0.5f * v * (1.0f + erff(v * 0.70710678118654752f));
}

// dot of a 64-float register array with 64 contiguous weights (uniform across warp)
__device__ __forceinline__ float dot64(const float* in, const float* __restrict__ W) {
    const float4* w4 = reinterpret_cast<const float4*>(W);
    float a0 = 0.f, a1 = 0.f, a2 = 0.f, a3 = 0.f;
#pragma unroll
    for (int i = 0; i < 16; i++) {
        float4 w = __ldg(w4 + i);
        a0 = fmaf(w.x, in[4 * i + 0], a0);
        a1 = fmaf(w.y, in[4 * i + 1], a1);
        a2 = fmaf(w.z, in[4 * i + 2], a2);
        a3 = fmaf(w.w, in[4 * i + 3], a3);
    }
    return (a0 + a1) + (a2 + a3);
}

__device__ __forceinline__ void ld64(float* r, const float* sh, int tid) {
#pragma unroll
    for (int i = 0; i < 64; i++) r[i] = sh[i * TT + tid];
}

// LayerNorm over 64 elements in shared (src), write to dst (may alias src)
__device__ __forceinline__ void ln_sh(const float* src, float* dst,
                                      const float* __restrict__ g,
                                      const float* __restrict__ b, int tid) {
    float m = 0.f;
#pragma unroll
    for (int j = 0; j < 64; j++) m += src[j * TT + tid];
    m *= (1.0f / 64.0f);
    float var = 0.f;
#pragma unroll
    for (int j = 0; j < 64; j++) { float d = src[j * TT + tid] - m; var = fmaf(d, d, var); }
    var *= (1.0f / 64.0f);
    float inv = rsqrtf(var + 1e-5f);
#pragma unroll
    for (int j = 0; j < 64; j++) {
        float d = (src[j * TT + tid] - m) * inv;
        dst[j * TT + tid] = fmaf(d, __ldg(g + j), __ldg(b + j));
    }
}

// out[j] = dot64(in, W_row_j) + b[j], streamed to shared
__device__ __forceinline__ void mv64_sh(const float* in, const float* __restrict__ W,
                                        const float* __restrict__ b, float* out, int tid) {
#pragma unroll 2
    for (int j = 0; j < 64; j++) {
        out[j * TT + tid] = dot64(in, W + j * 64) + __ldg(b + j);
    }
}

// s_vec := LN(s_vec + FFN(s_vec));  FFN hidden = 128, processed in 2 chunks of 64
__device__ __forceinline__ void ffn_block(float* s_vec, float* sA, float* sB,
        const float* __restrict__ w1, const float* __restrict__ b1,
        const float* __restrict__ w2, const float* __restrict__ b2,
        const float* __restrict__ g, const float* __restrict__ bb, int tid) {
    float vr[64];
    ld64(vr, s_vec, tid);
#pragma unroll
    for (int j = 0; j < 64; j++) sB[j * TT + tid] = vr[j] + __ldg(b2 + j);
#pragma unroll 1
    for (int c = 0; c < 2; c++) {
#pragma unroll 2
        for (int k = 0; k < 64; k++) {
            int r = c * 64 + k;
            sA[k * TT + tid] = gelu_exact(dot64(vr, w1 + r * 64) + __ldg(b1 + r));
        }
        float hr[64];
        ld64(hr, sA, tid);
#pragma unroll 2
        for (int j = 0; j < 64; j++) {
            sB[j * TT + tid] += dot64(hr, w2 + j * 128 + c * 64);
        }
    }
    ln_sh(sB, s_vec, g, bb, tid);
}

__global__ void __launch_bounds__(TT, 1)
trm_kernel(const float* __restrict__ x,
           const float* __restrict__ W_in,     const float* __restrict__ b_in,
           const float* __restrict__ g_in,     const float* __restrict__ be_in,
           const float* __restrict__ z_in_w,   const float* __restrict__ z_in_b,
           const float* __restrict__ z_out_w,  const float* __restrict__ z_out_b,
           const float* __restrict__ z_ffn_w1, const float* __restrict__ z_ffn_b1,
           const float* __restrict__ z_ffn_w2, const float* __restrict__ z_ffn_b2,
           const float* __restrict__ zn1_g,    const float* __restrict__ zn1_b,
           const float* __restrict__ zn2_g,    const float* __restrict__ zn2_b,
           const float* __restrict__ y_in_w,   const float* __restrict__ y_in_b,
           const float* __restrict__ y_out_w,  const float* __restrict__ y_out_b,
           const float* __restrict__ y_ffn_w1, const float* __restrict__ y_ffn_b1,
           const float* __restrict__ y_ffn_w2, const float* __restrict__ y_ffn_b2,
           const float* __restrict__ yn1_g,    const float* __restrict__ yn1_b,
           const float* __restrict__ yn2_g,    const float* __restrict__ yn2_b,
           const float* __restrict__ W_out,    const float* __restrict__ b_out,
           float* __restrict__ out, int Btotal) {
    extern __shared__ float sh[];
    float* sy  = sh + 0 * 64 * TT;
    float* sz  = sh + 1 * 64 * TT;
    float* skx = sh + 2 * 64 * TT;
    float* svx = sh + 3 * 64 * TT;
    float* sA  = sh + 4 * 64 * TT;
    float* sB  = sh + 5 * 64 * TT;

    const int tid = threadIdx.x;
    const int row = blockIdx.x * TT + tid;
    if (row >= Btotal) return;

    // ---------------- input projection: x_proj = gelu(LN(x @ W_in^T + b_in)) --------
    {
        const float4* xr = reinterpret_cast<const float4*>(x + (size_t)row * 200);
#pragma unroll
        for (int i = 0; i < 50; i++) {       // stage x row into sh[0..199] (temp use)
            float4 v = __ldg(xr + i);
            sh[(4 * i + 0) * TT + tid] = v.x;
            sh[(4 * i + 1) * TT + tid] = v.y;
            sh[(4 * i + 2) * TT + tid] = v.z;
            sh[(4 * i + 3) * TT + tid] = v.w;
        }
#pragma unroll 1
        for (int j = 0; j < 64; j++) {
            const float4* w4 = reinterpret_cast<const float4*>(W_in + j * 200);
            float a0 = 0.f, a1 = 0.f, a2 = 0.f, a3 = 0.f;
#pragma unroll
            for (int i = 0; i < 50; i++) {
                float4 w = __ldg(w4 + i);
                a0 = fmaf(w.x, sh[(4 * i + 0) * TT + tid], a0);
                a1 = fmaf(w.y, sh[(4 * i + 1) * TT + tid], a1);
                a2 = fmaf(w.z, sh[(4 * i + 2) * TT + tid], a2);
                a3 = fmaf(w.w, sh[(4 * i + 3) * TT + tid], a3);
            }
            sA[j * TT + tid] = (a0 + a1) + (a2 + a3) + __ldg(b_in + j);
        }
        ln_sh(sA, sA, g_in, be_in, tid);
#pragma unroll
        for (int j = 0; j < 64; j++) sA[j * TT + tid] = gelu_exact(sA[j * TT + tid]);
    }

    // ---------------- precompute k_x, v_x (loop-invariant); init y = z = 0 ----------
    {
        float xp[64];
        ld64(xp, sA, tid);
        mv64_sh(xp, z_in_w + 64 * 64,  z_in_b + 64,  skx, tid);   // k_x
        mv64_sh(xp, z_in_w + 128 * 64, z_in_b + 128, svx, tid);   // v_x
#pragma unroll
        for (int j = 0; j < 64; j++) { sy[j * TT + tid] = 0.f; sz[j * TT + tid] = 0.f; }
    }

    const float* Wq = z_in_w;
    const float* Wk = z_in_w + 64 * 64;
    const float* Wv = z_in_w + 128 * 64;

    // ---------------- 16 recursion steps --------------------------------------------
#pragma unroll 1
    for (int s = 0; s < NSTEPS; s++) {
        float yr[64], zr[64];
        ld64(yr, sy, tid);
        ld64(zr, sz, tid);

        // ---- attention (only q of token z is needed); att -> sA ----
#pragma unroll 1
        for (int h = 0; h < 4; h++) {
#pragma unroll 2
            for (int d = 0; d < 16; d++) {            // q_z head slice -> sB[0..15]
                int r = h * 16 + d;
                sB[d * TT + tid] = dot64(zr, Wq + r * 64) + __ldg(z_in_b + r);
            }
            float s0 = 0.f, s1 = 0.f, s2 = 0.f;
#pragma unroll 2
            for (int d = 0; d < 16; d++) {
                int r = h * 16 + d;
                float qd = sB[d * TT + tid];
                float bk = __ldg(z_in_b + 64 + r);
                s0 = fmaf(qd, skx[r * TT + tid], s0);
                s1 = fmaf(qd, dot64(yr, Wk + r * 64) + bk, s1);
                s2 = fmaf(qd, dot64(zr, Wk + r * 64) + bk, s2);
            }
            s0 *= 0.25f; s1 *= 0.25f; s2 *= 0.25f;    // 1/sqrt(D), D=16
            float mx = fmaxf(s0, fmaxf(s1, s2));
            float e0 = expf(s0 - mx), e1 = expf(s1 - mx), e2 = expf(s2 - mx);
            float rs = 1.0f / (e0 + e1 + e2);
            float w0 = e0 * rs, w1 = e1 * rs, w2v = e2 * rs;
#pragma unroll 2
            for (int d = 0; d < 16; d++) {
                int r = h * 16 + d;
                float bv = __ldg(z_in_b + 128 + r);
                float o = w0 * svx[r * TT + tid]
                        + w1  * (dot64(yr, Wv + r * 64) + bv)
                        + w2v * (dot64(zr, Wv + r * 64) + bv);
                sA[r * TT + tid] = o;
            }
        }

        // ---- z_res = LN(z + att @ z_out_w^T + z_out_b) ----
        {
            float ar[64];
            ld64(ar, sA, tid);
#pragma unroll 2
            for (int j = 0; j < 64; j++) {
                sB[j * TT + tid] = zr[j] + dot64(ar, z_out_w + j * 64) + __ldg(z_out_b + j);
            }
            ln_sh(sB, sz, zn1_g, zn1_b, tid);
        }

        // ---- z2 = LN(z_res + FFN_z(z_res)) ----
        ffn_block(sz, sA, sB, z_ffn_w1, z_ffn_b1, z_ffn_w2, z_ffn_b2, zn2_g, zn2_b, tid);

        // ---- cross attention: ca = (z2 @ Wv_y^T + bv_y) @ y_out_w^T + y_out_b ----
        {
            float z2r[64];
            ld64(z2r, sz, tid);
#pragma unroll 2
            for (int j = 0; j < 64; j++) {           // Wv_y = y_in_w rows [128:192]
                sA[j * TT + tid] = dot64(z2r, y_in_w + (128 + j) * 64) + __ldg(y_in_b + 128 + j);
            }
            float tr[64];
            ld64(tr, sA, tid);
#pragma unroll 2
            for (int j = 0; j < 64; j++) {
                sB[j * TT + tid] = sy[j * TT + tid] + dot64(tr, y_out_w + j * 64) + __ldg(y_out_b + j);
            }
            ln_sh(sB, sy, yn1_g, yn1_b, tid);
        }

        // ---- y2 = LN(y_res + FFN_y(y_res)) ----
        ffn_block(sy, sA, sB, y_ffn_w1, y_ffn_b1, y_ffn_w2, y_ffn_b2, yn2_g, yn2_b, tid);
    }

    // ---------------- output: (y @ W_out^T + b_out)[:, 0] ---------------------------
    {
        float acc = __ldg(b_out);
#pragma unroll
        for (int j = 0; j < 64; j++) acc = fmaf(sy[j * TT + tid], __ldg(W_out + j), acc);
        out[row] = acc;
    }
}

extern "C" void kernel_launch(void* const* d_in, const int* in_sizes, int n_in,
                              void* d_out, int out_size) {
    const float* x        = (const float*)d_in[0];
    const float* W_in     = (const float*)d_in[1];
    const float* b_in     = (const float*)d_in[2];
    const float* g_in     = (const float*)d_in[3];
    const float* be_in    = (const float*)d_in[4];
    const float* z_in_w   = (const float*)d_in[5];
    const float* z_in_b   = (const float*)d_in[6];
    const float* z_out_w  = (const float*)d_in[7];
    const float* z_out_b  = (const float*)d_in[8];
    const float* z_ffn_w1 = (const float*)d_in[9];
    const float* z_ffn_b1 = (const float*)d_in[10];
    const float* z_ffn_w2 = (const float*)d_in[11];
    const float* z_ffn_b2 = (const float*)d_in[12];
    const float* zn1_g    = (const float*)d_in[13];
    const float* zn1_b    = (const float*)d_in[14];
    const float* zn2_g    = (const float*)d_in[15];
    const float* zn2_b    = (const float*)d_in[16];
    const float* y_in_w   = (const float*)d_in[17];
    const float* y_in_b   = (const float*)d_in[18];
    const float* y_out_w  = (const float*)d_in[19];
    const float* y_out_b  = (const float*)d_in[20];
    const float* y_ffn_w1 = (const float*)d_in[21];
    const float* y_ffn_b1 = (const float*)d_in[22];
    const float* y_ffn_w2 = (const float*)d_in[23];
    const float* y_ffn_b2 = (const float*)d_in[24];
    const float* yn1_g    = (const float*)d_in[25];
    const float* yn1_b    = (const float*)d_in[26];
    const float* yn2_g    = (const float*)d_in[27];
    const float* yn2_b    = (const float*)d_in[28];
    const float* W_out    = (const float*)d_in[29];
    const float* b_out    = (const float*)d_in[30];
    float* out = (float*)d_out;

    int B = in_sizes[0] / 200;
    size_t smem = 384 * TT * sizeof(float);   // 196608 B
    cudaFuncSetAttribute(trm_kernel, cudaFuncAttributeMaxDynamicSharedMemorySize, (int)smem);

    dim3 grid((B + TT - 1) / TT);
    trm_kernel<<<grid, TT, smem>>>(x, W_in, b_in, g_in, be_in,
                                   z_in_w, z_in_b, z_out_w, z_out_b,
                                   z_ffn_w1, z_ffn_b1, z_ffn_w2, z_ffn_b2,
                                   zn1_g, zn1_b, zn2_g, zn2_b,
                                   y_in_w, y_in_b, y_out_w, y_out_b,
                                   y_ffn_w1, y_ffn_b1, y_ffn_w2, y_ffn_b2,
                                   yn1_g, yn1_b, yn2_g, yn2_b,
                                   W_out, b_out, out, B);
}